// round 14
// baseline (speedup 1.0000x reference)
#include <cuda_runtime.h>
#include <cuda_bf16.h>
#include <cuda_fp16.h>
#include <math.h>

#define N_NODES 50000
#define HIDDEN  128
#define HEADS   8
#define NH      (N_NODES * HIDDEN)
#define E_MAX   1600000
#define NCHUNK  ((N_NODES + 1023) / 1024)   // 49

// ---------------- scratch (device globals: allocation-free rule) ----------------
__device__ int   g_cnt_out[N_NODES];
__device__ int   g_cnt_in[N_NODES];
__device__ int   g_rowptr[N_NODES + 1];
__device__ int   g_cur[N_NODES];
__device__ __align__(16) int g_srt_src[E_MAX];
__device__ int   g_chunk[64];
__device__ float g_norm_out[N_NODES];
__device__ float g_norm_in[N_NODES];
__device__ __half g_hh[NH];                     // h * norm_out, fp16 (12.8 MB)
__device__ float g_agg[NH];                     // 25.6 MB (norms folded in)
__device__ float g_Qf[NH];                      // Q fp32 (25.6 MB)
__device__ __half g_KVh[2 * NH];                // K|V interleaved per lane: 8 halfs = 4K + 4V (25.6 MB)
__device__ __nv_bfloat16 g_Wt_hi[3][128 * 128]; // W^T split-bf16 high parts
__device__ __nv_bfloat16 g_Wt_lo[3][128 * 128]; // W^T split-bf16 low parts

// ---------------- 0: fused setup: zero counters + W -> transposed split-bf16 ----------------
__global__ void setup_kernel(const float* __restrict__ Wq, const float* __restrict__ Wk,
                             const float* __restrict__ Wv) {
    int t = blockIdx.x * 256 + threadIdx.x;
    if (t < N_NODES) { g_cnt_out[t] = 0; g_cnt_in[t] = 0; }
    if (t < 3 * 128 * 128) {
        int mat = t >> 14, rem = t & 16383;
        int n = rem >> 7, k = rem & 127;
        const float* W = (mat == 0) ? Wq : (mat == 1) ? Wk : Wv;
        float x = W[k * 128 + n];
        __nv_bfloat16 h = __float2bfloat16(x);
        g_Wt_hi[mat][n * 128 + k] = h;
        g_Wt_lo[mat][n * 128 + k] = __float2bfloat16(x - __bfloat162float(h));
    }
}

// ---------------- 1: degree histograms ----------------
__global__ void degree_kernel(const int* __restrict__ src, const int* __restrict__ dst, int E) {
    int e = blockIdx.x * blockDim.x + threadIdx.x;
    if (e < E) {
        atomicAdd(&g_cnt_out[src[e]], 1);
        atomicAdd(&g_cnt_in[dst[e]], 1);
    }
}

// ---------------- 2a: per-1024-chunk inclusive scan of in-degrees ----------------
__global__ void scan_local() {
    __shared__ int wsum[32];
    const int tid = threadIdx.x, lane = tid & 31, wid = tid >> 5;
    int i = blockIdx.x * 1024 + tid;
    int x = (i < N_NODES) ? g_cnt_in[i] : 0;
    #pragma unroll
    for (int o = 1; o < 32; o <<= 1) {
        int t = __shfl_up_sync(0xffffffffu, x, o);
        if (lane >= o) x += t;
    }
    if (lane == 31) wsum[wid] = x;
    __syncthreads();
    if (wid == 0) {
        int w = wsum[lane];
        #pragma unroll
        for (int o = 1; o < 32; o <<= 1) {
            int t = __shfl_up_sync(0xffffffffu, w, o);
            if (lane >= o) w += t;
        }
        wsum[lane] = w;
    }
    __syncthreads();
    int incl = x + (wid > 0 ? wsum[wid - 1] : 0);
    if (i < N_NODES) g_rowptr[i + 1] = incl;
    if (tid == 1023) g_chunk[blockIdx.x] = incl;
}

// ---------------- 2b: finalize rowptr + cursors + norms (chunk scan inlined per-block) ----------------
__global__ void finalize_csr() {
    __shared__ int pref[64];
    const int tid = threadIdx.x;
    if (tid < 64) pref[tid] = (tid < NCHUNK) ? g_chunk[tid] : 0;
    __syncthreads();
    #pragma unroll
    for (int off = 1; off < 64; off <<= 1) {
        int v = 0;
        if (tid < 64 && tid >= off) v = pref[tid - off];
        __syncthreads();
        if (tid < 64) pref[tid] += v;
        __syncthreads();
    }
    int i = blockIdx.x * blockDim.x + tid;
    if (i < N_NODES) {
        int c = i >> 10;
        int inc = g_rowptr[i + 1] + ((c > 0) ? pref[c - 1] : 0);
        g_rowptr[i + 1] = inc;
        int cin = g_cnt_in[i];
        g_cur[i] = inc - cin;
        g_norm_in[i]  = rsqrtf(fmaxf((float)cin, 1.f));
        g_norm_out[i] = rsqrtf(fmaxf((float)g_cnt_out[i], 1.f));
        if (i == 0) g_rowptr[0] = 0;
    }
}

// ---------------- 3: fused counting-sort bucket fill + prescale h*norm_out -> fp16 ----------------
// E == NH/4 == 1.6M: one grid covers both jobs.
__global__ void bucket_prescale(const float* __restrict__ h,
                                const int* __restrict__ src, const int* __restrict__ dst, int E) {
    int i = blockIdx.x * 256 + threadIdx.x;
    if (i < E) {
        int p = atomicAdd(&g_cur[dst[i]], 1);
        g_srt_src[p] = src[i];
    }
    if (i < NH / 4) {
        int node = i >> 5;
        float no = g_norm_out[node];
        float4 a = ((const float4*)h)[i];
        __half2 h0 = __floats2half2_rn(a.x * no, a.y * no);
        __half2 h1 = __floats2half2_rn(a.z * no, a.w * no);
        uint2 o;
        o.x = *reinterpret_cast<unsigned*>(&h0);
        o.y = *reinterpret_cast<unsigned*>(&h1);
        ((uint2*)g_hh)[i] = o;
    }
}

// ---------------- 4: gather-aggregate (fp16 prescaled h, int4 srt loads) ----------------
__device__ __forceinline__ void acc_h2(float4& acc, uint2 raw) {
    float2 f0 = __half22float2(*reinterpret_cast<__half2*>(&raw.x));
    float2 f1 = __half22float2(*reinterpret_cast<__half2*>(&raw.y));
    acc.x += f0.x; acc.y += f0.y; acc.z += f1.x; acc.w += f1.y;
}

__global__ __launch_bounds__(256) void agg_gather() {
    int node = (blockIdx.x * blockDim.x + threadIdx.x) >> 5;
    int lane = threadIdx.x & 31;
    if (node >= N_NODES) return;
    int beg = g_rowptr[node], end = g_rowptr[node + 1];
    const uint2* h2 = (const uint2*)g_hh;
    float4 acc = make_float4(0.f, 0.f, 0.f, 0.f);

    int j = beg;
    int ja = (beg + 3) & ~3;           // first 16B-aligned index
    if (ja > end) ja = end;
    for (; j < ja; j++)
        acc_h2(acc, h2[(size_t)g_srt_src[j] * 32 + lane]);
    for (; j + 4 <= end; j += 4) {
        int4 s4 = *(const int4*)&g_srt_src[j];
        uint2 a = h2[(size_t)s4.x * 32 + lane];
        uint2 b = h2[(size_t)s4.y * 32 + lane];
        uint2 c = h2[(size_t)s4.z * 32 + lane];
        uint2 d = h2[(size_t)s4.w * 32 + lane];
        acc_h2(acc, a); acc_h2(acc, b); acc_h2(acc, c); acc_h2(acc, d);
    }
    for (; j < end; j++)
        acc_h2(acc, h2[(size_t)g_srt_src[j] * 32 + lane]);

    float ni = g_norm_in[node];
    acc.x *= ni; acc.y *= ni; acc.z *= ni; acc.w *= ni;
    *(float4*)&g_agg[(size_t)node * 128 + (lane << 2)] = acc;
}

// ---------------- 5: QKV GEMM via split-bf16 tensor cores ----------------
__device__ __forceinline__ void mma16816(float* c, const unsigned* a, unsigned b0, unsigned b1) {
    asm volatile(
        "mma.sync.aligned.m16n8k16.row.col.f32.bf16.bf16.f32 "
        "{%0,%1,%2,%3}, {%4,%5,%6,%7}, {%8,%9}, {%0,%1,%2,%3};\n"
        : "+f"(c[0]), "+f"(c[1]), "+f"(c[2]), "+f"(c[3])
        : "r"(a[0]), "r"(a[1]), "r"(a[2]), "r"(a[3]), "r"(b0), "r"(b1));
}

// M-tile 128 x N 128, K streamed in 32-chunks. 8 warps, warp w owns rows [16w,16w+16).
__global__ __launch_bounds__(256, 2) void gemm_qkv_mma(
    const float* __restrict__ bq, const float* __restrict__ bk, const float* __restrict__ bv)
{
    const int mat = blockIdx.y;
    const float* bias = (mat == 0) ? bq : (mat == 1) ? bk : bv;
    const __nv_bfloat16* WtH = g_Wt_hi[mat];
    const __nv_bfloat16* WtL = g_Wt_lo[mat];

    __shared__ __nv_bfloat16 sA_hi[128 * 40];
    __shared__ __nv_bfloat16 sA_lo[128 * 40];
    __shared__ __nv_bfloat16 sB_hi[128 * 40];
    __shared__ __nv_bfloat16 sB_lo[128 * 40];

    const int tid = threadIdx.x;
    const int warp = tid >> 5, lane = tid & 31;
    const int g = lane >> 2, tg = lane & 3;
    const int row0 = blockIdx.x * 128;

    float acc[16][4];
    #pragma unroll
    for (int i = 0; i < 16; i++)
        #pragma unroll
        for (int j = 0; j < 4; j++) acc[i][j] = 0.f;

    const int r = tid >> 1;
    const int hh = tid & 1;

    for (int k0 = 0; k0 < 128; k0 += 32) {
        float xs[16];
        int arow = row0 + r;
        if (arow < N_NODES) {
            const float4* p = (const float4*)(g_agg + (size_t)arow * 128 + k0 + hh * 16);
            float4 a = p[0], b = p[1], c = p[2], d = p[3];
            xs[0]=a.x; xs[1]=a.y; xs[2]=a.z; xs[3]=a.w;
            xs[4]=b.x; xs[5]=b.y; xs[6]=b.z; xs[7]=b.w;
            xs[8]=c.x; xs[9]=c.y; xs[10]=c.z; xs[11]=c.w;
            xs[12]=d.x; xs[13]=d.y; xs[14]=d.z; xs[15]=d.w;
        } else {
            #pragma unroll
            for (int i = 0; i < 16; i++) xs[i] = 0.f;
        }
        __align__(16) __nv_bfloat16 hi[16], lo[16];
        #pragma unroll
        for (int i = 0; i < 16; i++) {
            hi[i] = __float2bfloat16(xs[i]);
            lo[i] = __float2bfloat16(xs[i] - __bfloat162float(hi[i]));
        }
        *(int4*)&sA_hi[r * 40 + hh * 16]     = ((int4*)hi)[0];
        *(int4*)&sA_hi[r * 40 + hh * 16 + 8] = ((int4*)hi)[1];
        *(int4*)&sA_lo[r * 40 + hh * 16]     = ((int4*)lo)[0];
        *(int4*)&sA_lo[r * 40 + hh * 16 + 8] = ((int4*)lo)[1];

        const int4* srcH = (const int4*)(WtH + r * 128 + k0 + hh * 16);
        const int4* srcL = (const int4*)(WtL + r * 128 + k0 + hh * 16);
        *(int4*)&sB_hi[r * 40 + hh * 16]     = srcH[0];
        *(int4*)&sB_hi[r * 40 + hh * 16 + 8] = srcH[1];
        *(int4*)&sB_lo[r * 40 + hh * 16]     = srcL[0];
        *(int4*)&sB_lo[r * 40 + hh * 16 + 8] = srcL[1];
        __syncthreads();

        const unsigned* pAH = (const unsigned*)sA_hi;
        const unsigned* pAL = (const unsigned*)sA_lo;
        const unsigned* pBH = (const unsigned*)sB_hi;
        const unsigned* pBL = (const unsigned*)sB_lo;
        const int ra = warp * 16 + g;

        #pragma unroll
        for (int kw = 0; kw <= 8; kw += 8) {
            unsigned aH[4], aL[4];
            aH[0] = pAH[ra * 20 + kw + tg];
            aH[1] = pAH[(ra + 8) * 20 + kw + tg];
            aH[2] = pAH[ra * 20 + kw + tg + 4];
            aH[3] = pAH[(ra + 8) * 20 + kw + tg + 4];
            aL[0] = pAL[ra * 20 + kw + tg];
            aL[1] = pAL[(ra + 8) * 20 + kw + tg];
            aL[2] = pAL[ra * 20 + kw + tg + 4];
            aL[3] = pAL[(ra + 8) * 20 + kw + tg + 4];
            #pragma unroll
            for (int nt = 0; nt < 16; nt++) {
                int nb = nt * 8 + g;
                unsigned bH0 = pBH[nb * 20 + kw + tg];
                unsigned bH1 = pBH[nb * 20 + kw + tg + 4];
                unsigned bL0 = pBL[nb * 20 + kw + tg];
                unsigned bL1 = pBL[nb * 20 + kw + tg + 4];
                mma16816(acc[nt], aH, bH0, bH1);
                mma16816(acc[nt], aH, bL0, bL1);
                mma16816(acc[nt], aL, bH0, bH1);
            }
        }
        __syncthreads();
    }

    // --- epilogue: bias + relu; Q fp32; K/V fp16 interleaved per lane ---
    const int gr0 = row0 + warp * 16 + g;
    const int gr1 = gr0 + 8;
    #pragma unroll
    for (int nt = 0; nt < 16; nt++) {
        int c = nt * 8 + tg * 2;
        float2 bb = *(const float2*)&bias[c];
        float v0 = fmaxf(acc[nt][0] + bb.x, 0.f);
        float v1 = fmaxf(acc[nt][1] + bb.y, 0.f);
        float v2 = fmaxf(acc[nt][2] + bb.x, 0.f);
        float v3 = fmaxf(acc[nt][3] + bb.y, 0.f);
        if (mat == 0) {
            if (gr0 < N_NODES) *(float2*)&g_Qf[(size_t)gr0 * 128 + c] = make_float2(v0, v1);
            if (gr1 < N_NODES) *(float2*)&g_Qf[(size_t)gr1 * 128 + c] = make_float2(v2, v3);
        } else {
            size_t off = ((size_t)(c >> 2) << 3) + (c & 3) + ((mat == 2) ? 4 : 0);
            if (gr0 < N_NODES) *(__half2*)&g_KVh[(size_t)gr0 * 256 + off] = __floats2half2_rn(v0, v1);
            if (gr1 < N_NODES) *(__half2*)&g_KVh[(size_t)gr1 * 256 + off] = __floats2half2_rn(v2, v3);
        }
    }
}

// ---------------- 6: gather-attention + finalize ----------------
// per lane: one uint4 = 4 K-feats + 4 V-feats (fp16). Score math in fp16 (HFMA2).
__device__ __forceinline__ float edge_score_kv(uint4 kv, __half2 q01, __half2 q23) {
    __half2 k01 = *reinterpret_cast<__half2*>(&kv.x);
    __half2 k23 = *reinterpret_cast<__half2*>(&kv.y);
    __half2 p2 = __hfma2(k01, q01, __hmul2(k23, q23));
    float p = __half2float(__hadd(__low2half(p2), __high2half(p2)));
    p += __shfl_xor_sync(0xffffffffu, p, 1);
    p += __shfl_xor_sync(0xffffffffu, p, 2);
    return __expf(fminf(fmaxf(p * 0.25f, -10.f), 10.f));
}

__device__ __forceinline__ void acc_kv(float4& acc, uint4 kv, float sc) {
    float2 f0 = __half22float2(*reinterpret_cast<__half2*>(&kv.z));
    float2 f1 = __half22float2(*reinterpret_cast<__half2*>(&kv.w));
    acc.x += f0.x * sc; acc.y += f0.y * sc; acc.z += f1.x * sc; acc.w += f1.y * sc;
}

__global__ __launch_bounds__(256) void attn_gather(float* __restrict__ out) {
    int node = (blockIdx.x * blockDim.x + threadIdx.x) >> 5;
    int lane = threadIdx.x & 31;
    if (node >= N_NODES) return;
    int beg = g_rowptr[node], end = g_rowptr[node + 1];

    const float4* Q4 = (const float4*)g_Qf;
    const uint4* KV4 = (const uint4*)g_KVh;

    float4 q = Q4[(size_t)node * 32 + lane];
    __half2 q01 = __floats2half2_rn(q.x, q.y);
    __half2 q23 = __floats2half2_rn(q.z, q.w);
    float4 acc = make_float4(0.f, 0.f, 0.f, 0.f);
    float z = 0.f;

    int j = beg;
    int ja = (beg + 3) & ~3;
    if (ja > end) ja = end;
    for (; j < ja; j++) {
        uint4 kv = KV4[(size_t)g_srt_src[j] * 32 + lane];
        float sc = edge_score_kv(kv, q01, q23);
        acc_kv(acc, kv, sc);
        z += sc;
    }
    for (; j + 4 <= end; j += 4) {
        int4 s4 = *(const int4*)&g_srt_src[j];
        uint4 kv0 = KV4[(size_t)s4.x * 32 + lane];
        uint4 kv1 = KV4[(size_t)s4.y * 32 + lane];
        uint4 kv2 = KV4[(size_t)s4.z * 32 + lane];
        uint4 kv3 = KV4[(size_t)s4.w * 32 + lane];
        float sc0 = edge_score_kv(kv0, q01, q23);
        float sc1 = edge_score_kv(kv1, q01, q23);
        float sc2 = edge_score_kv(kv2, q01, q23);
        float sc3 = edge_score_kv(kv3, q01, q23);
        acc_kv(acc, kv0, sc0); acc_kv(acc, kv1, sc1);
        acc_kv(acc, kv2, sc2); acc_kv(acc, kv3, sc3);
        z += (sc0 + sc1) + (sc2 + sc3);
    }
    for (; j < end; j++) {
        uint4 kv = KV4[(size_t)g_srt_src[j] * 32 + lane];
        float sc = edge_score_kv(kv, q01, q23);
        acc_kv(acc, kv, sc);
        z += sc;
    }

    float inv = 1.f / (z + 1e-6f);
    acc.x *= inv; acc.y *= inv; acc.z *= inv; acc.w *= inv;
    *(float4*)&out[(size_t)node * 128 + (lane << 2)] = acc;
}

// ---------------- launcher ----------------
extern "C" void kernel_launch(void* const* d_in, const int* in_sizes, int n_in,
                              void* d_out, int out_size) {
    const float* h  = (const float*)d_in[0];
    const float* Wq = (const float*)d_in[1];
    const float* bq = (const float*)d_in[2];
    const float* Wk = (const float*)d_in[3];
    const float* bk = (const float*)d_in[4];
    const float* Wv = (const float*)d_in[5];
    const float* bv = (const float*)d_in[6];
    const int*  src = (const int*)d_in[7];
    const int*  dst = (const int*)d_in[8];
    const int E = in_sizes[7];
    float* out = (float*)d_out;

    setup_kernel<<<(N_NODES + 255) / 256, 256>>>(Wq, Wk, Wv);
    degree_kernel<<<(E + 255) / 256, 256>>>(src, dst, E);
    scan_local<<<NCHUNK, 1024>>>();
    finalize_csr<<<(N_NODES + 255) / 256, 256>>>();

    int nmax = (E > NH / 4) ? E : NH / 4;
    bucket_prescale<<<(nmax + 255) / 256, 256>>>(h, src, dst, E);

    int nwblocks = (N_NODES * 32 + 255) / 256;
    agg_gather<<<nwblocks, 256>>>();

    dim3 gg((N_NODES + 127) / 128, 3);
    gemm_qkv_mma<<<gg, 256>>>(bq, bk, bv);

    attn_gather<<<nwblocks, 256>>>(out);
}

// round 16
// speedup vs baseline: 1.4300x; 1.4300x over previous
#include <cuda_runtime.h>
#include <cuda_bf16.h>
#include <cuda_fp16.h>
#include <math.h>

#define N_NODES 50000
#define HIDDEN  128
#define HEADS   8
#define NH      (N_NODES * HIDDEN)
#define E_MAX   1600000
#define NCHUNK  ((N_NODES + 1023) / 1024)   // 49

// ---------------- scratch (device globals: allocation-free rule) ----------------
__device__ int   g_cnt_out[N_NODES];
__device__ int   g_cnt_in[N_NODES];
__device__ int   g_rowptr[N_NODES + 1];
__device__ int   g_cur[N_NODES];
__device__ __align__(16) int g_srt_src[E_MAX];
__device__ int   g_chunk[64];
__device__ float g_norm_out[N_NODES];
__device__ float g_norm_in[N_NODES];
__device__ __half g_hh[NH];                     // h * norm_out, fp16 (12.8 MB)
__device__ float g_agg[NH];                     // 25.6 MB (norms folded in)
__device__ float g_Qf[NH];                      // Q fp32 (25.6 MB)
__device__ __half g_KVh[2 * NH];                // K|V interleaved per lane: 8 halfs = 4K + 4V (25.6 MB)
__device__ __nv_bfloat16 g_Wt_hi[3][128 * 128]; // W^T split-bf16 high parts
__device__ __nv_bfloat16 g_Wt_lo[3][128 * 128]; // W^T split-bf16 low parts

// ---------------- 0: fused setup: zero counters + W -> transposed split-bf16 ----------------
__global__ void setup_kernel(const float* __restrict__ Wq, const float* __restrict__ Wk,
                             const float* __restrict__ Wv) {
    int t = blockIdx.x * 256 + threadIdx.x;
    if (t < N_NODES) { g_cnt_out[t] = 0; g_cnt_in[t] = 0; }
    if (t < 3 * 128 * 128) {
        int mat = t >> 14, rem = t & 16383;
        int n = rem >> 7, k = rem & 127;
        const float* W = (mat == 0) ? Wq : (mat == 1) ? Wk : Wv;
        float x = W[k * 128 + n];
        __nv_bfloat16 h = __float2bfloat16(x);
        g_Wt_hi[mat][n * 128 + k] = h;
        g_Wt_lo[mat][n * 128 + k] = __float2bfloat16(x - __bfloat162float(h));
    }
}

// ---------------- 1: degree histograms ----------------
__global__ void degree_kernel(const int* __restrict__ src, const int* __restrict__ dst, int E) {
    int e = blockIdx.x * blockDim.x + threadIdx.x;
    if (e < E) {
        atomicAdd(&g_cnt_out[src[e]], 1);
        atomicAdd(&g_cnt_in[dst[e]], 1);
    }
}

// ---------------- 2a: per-1024-chunk inclusive scan of in-degrees ----------------
__global__ void scan_local() {
    __shared__ int wsum[32];
    const int tid = threadIdx.x, lane = tid & 31, wid = tid >> 5;
    int i = blockIdx.x * 1024 + tid;
    int x = (i < N_NODES) ? g_cnt_in[i] : 0;
    #pragma unroll
    for (int o = 1; o < 32; o <<= 1) {
        int t = __shfl_up_sync(0xffffffffu, x, o);
        if (lane >= o) x += t;
    }
    if (lane == 31) wsum[wid] = x;
    __syncthreads();
    if (wid == 0) {
        int w = wsum[lane];
        #pragma unroll
        for (int o = 1; o < 32; o <<= 1) {
            int t = __shfl_up_sync(0xffffffffu, w, o);
            if (lane >= o) w += t;
        }
        wsum[lane] = w;
    }
    __syncthreads();
    int incl = x + (wid > 0 ? wsum[wid - 1] : 0);
    if (i < N_NODES) g_rowptr[i + 1] = incl;
    if (tid == 1023) g_chunk[blockIdx.x] = incl;
}

// ---------------- 2b: finalize rowptr + cursors + norms (chunk scan inlined per-block) ----------------
__global__ void finalize_csr() {
    __shared__ int pref[64];
    const int tid = threadIdx.x;
    if (tid < 64) pref[tid] = (tid < NCHUNK) ? g_chunk[tid] : 0;
    __syncthreads();
    #pragma unroll
    for (int off = 1; off < 64; off <<= 1) {
        int v = 0;
        if (tid < 64 && tid >= off) v = pref[tid - off];
        __syncthreads();
        if (tid < 64) pref[tid] += v;
        __syncthreads();
    }
    int i = blockIdx.x * blockDim.x + tid;
    if (i < N_NODES) {
        int c = i >> 10;
        int inc = g_rowptr[i + 1] + ((c > 0) ? pref[c - 1] : 0);
        g_rowptr[i + 1] = inc;
        int cin = g_cnt_in[i];
        g_cur[i] = inc - cin;
        g_norm_in[i]  = rsqrtf(fmaxf((float)cin, 1.f));
        g_norm_out[i] = rsqrtf(fmaxf((float)g_cnt_out[i], 1.f));
        if (i == 0) g_rowptr[0] = 0;
    }
}

// ---------------- 3: fused counting-sort bucket fill + prescale h*norm_out -> fp16 ----------------
// E == NH/4 == 1.6M: one grid covers both jobs.
__global__ void bucket_prescale(const float* __restrict__ h,
                                const int* __restrict__ src, const int* __restrict__ dst, int E) {
    int i = blockIdx.x * 256 + threadIdx.x;
    if (i < E) {
        int p = atomicAdd(&g_cur[dst[i]], 1);
        g_srt_src[p] = src[i];
    }
    if (i < NH / 4) {
        int node = i >> 5;
        float no = g_norm_out[node];
        float4 a = ((const float4*)h)[i];
        __half2 h0 = __floats2half2_rn(a.x * no, a.y * no);
        __half2 h1 = __floats2half2_rn(a.z * no, a.w * no);
        uint2 o;
        o.x = *reinterpret_cast<unsigned*>(&h0);
        o.y = *reinterpret_cast<unsigned*>(&h1);
        ((uint2*)g_hh)[i] = o;
    }
}

// ---------------- 4: gather-aggregate (fp16 prescaled h) ----------------
__device__ __forceinline__ void acc_h2(float4& acc, uint2 raw) {
    float2 f0 = __half22float2(*reinterpret_cast<__half2*>(&raw.x));
    float2 f1 = __half22float2(*reinterpret_cast<__half2*>(&raw.y));
    acc.x += f0.x; acc.y += f0.y; acc.z += f1.x; acc.w += f1.y;
}

__global__ __launch_bounds__(256) void agg_gather() {
    int node = (blockIdx.x * blockDim.x + threadIdx.x) >> 5;
    int lane = threadIdx.x & 31;
    if (node >= N_NODES) return;
    int beg = g_rowptr[node], end = g_rowptr[node + 1];
    const uint2* h2 = (const uint2*)g_hh;
    float4 acc = make_float4(0.f, 0.f, 0.f, 0.f);
    int j = beg;
    for (; j + 4 <= end; j += 4) {
        int s0 = g_srt_src[j], s1 = g_srt_src[j + 1], s2 = g_srt_src[j + 2], s3 = g_srt_src[j + 3];
        uint2 a = h2[(size_t)s0 * 32 + lane];
        uint2 b = h2[(size_t)s1 * 32 + lane];
        uint2 c = h2[(size_t)s2 * 32 + lane];
        uint2 d = h2[(size_t)s3 * 32 + lane];
        acc_h2(acc, a); acc_h2(acc, b); acc_h2(acc, c); acc_h2(acc, d);
    }
    for (; j < end; j++) {
        int s = g_srt_src[j];
        acc_h2(acc, h2[(size_t)s * 32 + lane]);
    }
    float ni = g_norm_in[node];
    acc.x *= ni; acc.y *= ni; acc.z *= ni; acc.w *= ni;
    *(float4*)&g_agg[(size_t)node * 128 + (lane << 2)] = acc;
}

// ---------------- 5: QKV GEMM via split-bf16 tensor cores ----------------
__device__ __forceinline__ void mma16816(float* c, const unsigned* a, unsigned b0, unsigned b1) {
    asm volatile(
        "mma.sync.aligned.m16n8k16.row.col.f32.bf16.bf16.f32 "
        "{%0,%1,%2,%3}, {%4,%5,%6,%7}, {%8,%9}, {%0,%1,%2,%3};\n"
        : "+f"(c[0]), "+f"(c[1]), "+f"(c[2]), "+f"(c[3])
        : "r"(a[0]), "r"(a[1]), "r"(a[2]), "r"(a[3]), "r"(b0), "r"(b1));
}

// M-tile 128 x N 128, K streamed in 32-chunks. 8 warps, warp w owns rows [16w,16w+16).
__global__ __launch_bounds__(256, 2) void gemm_qkv_mma(
    const float* __restrict__ bq, const float* __restrict__ bk, const float* __restrict__ bv)
{
    const int mat = blockIdx.y;
    const float* bias = (mat == 0) ? bq : (mat == 1) ? bk : bv;
    const __nv_bfloat16* WtH = g_Wt_hi[mat];
    const __nv_bfloat16* WtL = g_Wt_lo[mat];

    __shared__ __nv_bfloat16 sA_hi[128 * 40];
    __shared__ __nv_bfloat16 sA_lo[128 * 40];
    __shared__ __nv_bfloat16 sB_hi[128 * 40];
    __shared__ __nv_bfloat16 sB_lo[128 * 40];

    const int tid = threadIdx.x;
    const int warp = tid >> 5, lane = tid & 31;
    const int g = lane >> 2, tg = lane & 3;
    const int row0 = blockIdx.x * 128;

    float acc[16][4];
    #pragma unroll
    for (int i = 0; i < 16; i++)
        #pragma unroll
        for (int j = 0; j < 4; j++) acc[i][j] = 0.f;

    const int r = tid >> 1;
    const int hh = tid & 1;

    for (int k0 = 0; k0 < 128; k0 += 32) {
        float xs[16];
        int arow = row0 + r;
        if (arow < N_NODES) {
            const float4* p = (const float4*)(g_agg + (size_t)arow * 128 + k0 + hh * 16);
            float4 a = p[0], b = p[1], c = p[2], d = p[3];
            xs[0]=a.x; xs[1]=a.y; xs[2]=a.z; xs[3]=a.w;
            xs[4]=b.x; xs[5]=b.y; xs[6]=b.z; xs[7]=b.w;
            xs[8]=c.x; xs[9]=c.y; xs[10]=c.z; xs[11]=c.w;
            xs[12]=d.x; xs[13]=d.y; xs[14]=d.z; xs[15]=d.w;
        } else {
            #pragma unroll
            for (int i = 0; i < 16; i++) xs[i] = 0.f;
        }
        __align__(16) __nv_bfloat16 hi[16], lo[16];
        #pragma unroll
        for (int i = 0; i < 16; i++) {
            hi[i] = __float2bfloat16(xs[i]);
            lo[i] = __float2bfloat16(xs[i] - __bfloat162float(hi[i]));
        }
        *(int4*)&sA_hi[r * 40 + hh * 16]     = ((int4*)hi)[0];
        *(int4*)&sA_hi[r * 40 + hh * 16 + 8] = ((int4*)hi)[1];
        *(int4*)&sA_lo[r * 40 + hh * 16]     = ((int4*)lo)[0];
        *(int4*)&sA_lo[r * 40 + hh * 16 + 8] = ((int4*)lo)[1];

        const int4* srcH = (const int4*)(WtH + r * 128 + k0 + hh * 16);
        const int4* srcL = (const int4*)(WtL + r * 128 + k0 + hh * 16);
        *(int4*)&sB_hi[r * 40 + hh * 16]     = srcH[0];
        *(int4*)&sB_hi[r * 40 + hh * 16 + 8] = srcH[1];
        *(int4*)&sB_lo[r * 40 + hh * 16]     = srcL[0];
        *(int4*)&sB_lo[r * 40 + hh * 16 + 8] = srcL[1];
        __syncthreads();

        const unsigned* pAH = (const unsigned*)sA_hi;
        const unsigned* pAL = (const unsigned*)sA_lo;
        const unsigned* pBH = (const unsigned*)sB_hi;
        const unsigned* pBL = (const unsigned*)sB_lo;
        const int ra = warp * 16 + g;

        #pragma unroll
        for (int kw = 0; kw <= 8; kw += 8) {
            unsigned aH[4], aL[4];
            aH[0] = pAH[ra * 20 + kw + tg];
            aH[1] = pAH[(ra + 8) * 20 + kw + tg];
            aH[2] = pAH[ra * 20 + kw + tg + 4];
            aH[3] = pAH[(ra + 8) * 20 + kw + tg + 4];
            aL[0] = pAL[ra * 20 + kw + tg];
            aL[1] = pAL[(ra + 8) * 20 + kw + tg];
            aL[2] = pAL[ra * 20 + kw + tg + 4];
            aL[3] = pAL[(ra + 8) * 20 + kw + tg + 4];
            #pragma unroll
            for (int nt = 0; nt < 16; nt++) {
                int nb = nt * 8 + g;
                unsigned bH0 = pBH[nb * 20 + kw + tg];
                unsigned bH1 = pBH[nb * 20 + kw + tg + 4];
                unsigned bL0 = pBL[nb * 20 + kw + tg];
                unsigned bL1 = pBL[nb * 20 + kw + tg + 4];
                mma16816(acc[nt], aH, bH0, bH1);
                mma16816(acc[nt], aH, bL0, bL1);
                mma16816(acc[nt], aL, bH0, bH1);
            }
        }
        __syncthreads();
    }

    // --- epilogue: bias + relu; Q fp32; K/V fp16 interleaved per lane ---
    const int gr0 = row0 + warp * 16 + g;
    const int gr1 = gr0 + 8;
    #pragma unroll
    for (int nt = 0; nt < 16; nt++) {
        int c = nt * 8 + tg * 2;
        float2 bb = *(const float2*)&bias[c];
        float v0 = fmaxf(acc[nt][0] + bb.x, 0.f);
        float v1 = fmaxf(acc[nt][1] + bb.y, 0.f);
        float v2 = fmaxf(acc[nt][2] + bb.x, 0.f);
        float v3 = fmaxf(acc[nt][3] + bb.y, 0.f);
        if (mat == 0) {
            if (gr0 < N_NODES) *(float2*)&g_Qf[(size_t)gr0 * 128 + c] = make_float2(v0, v1);
            if (gr1 < N_NODES) *(float2*)&g_Qf[(size_t)gr1 * 128 + c] = make_float2(v2, v3);
        } else {
            size_t off = ((size_t)(c >> 2) << 3) + (c & 3) + ((mat == 2) ? 4 : 0);
            if (gr0 < N_NODES) *(__half2*)&g_KVh[(size_t)gr0 * 256 + off] = __floats2half2_rn(v0, v1);
            if (gr1 < N_NODES) *(__half2*)&g_KVh[(size_t)gr1 * 256 + off] = __floats2half2_rn(v2, v3);
        }
    }
}

// ---------------- 6: gather-attention + finalize ----------------
// per lane: one uint4 = 4 K-feats + 4 V-feats (fp16). fp32 score math (proven r11 config).
__device__ __forceinline__ float edge_score_kv(uint4 kv, float4 q) {
    float2 k01 = __half22float2(*reinterpret_cast<__half2*>(&kv.x));
    float2 k23 = __half22float2(*reinterpret_cast<__half2*>(&kv.y));
    float p = k01.x * q.x + k01.y * q.y + k23.x * q.z + k23.y * q.w;
    p += __shfl_xor_sync(0xffffffffu, p, 1);
    p += __shfl_xor_sync(0xffffffffu, p, 2);
    return __expf(fminf(fmaxf(p * 0.25f, -10.f), 10.f));
}

__device__ __forceinline__ void acc_kv(float4& acc, uint4 kv, float sc) {
    float2 f0 = __half22float2(*reinterpret_cast<__half2*>(&kv.z));
    float2 f1 = __half22float2(*reinterpret_cast<__half2*>(&kv.w));
    acc.x += f0.x * sc; acc.y += f0.y * sc; acc.z += f1.x * sc; acc.w += f1.y * sc;
}

__global__ __launch_bounds__(256) void attn_gather(float* __restrict__ out) {
    int node = (blockIdx.x * blockDim.x + threadIdx.x) >> 5;
    int lane = threadIdx.x & 31;
    if (node >= N_NODES) return;
    int beg = g_rowptr[node], end = g_rowptr[node + 1];

    const float4* Q4 = (const float4*)g_Qf;
    const uint4* KV4 = (const uint4*)g_KVh;

    float4 q = Q4[(size_t)node * 32 + lane];
    float4 acc = make_float4(0.f, 0.f, 0.f, 0.f);
    float z = 0.f;

    int j = beg;
    for (; j + 4 <= end; j += 4) {
        int s0 = g_srt_src[j], s1 = g_srt_src[j + 1], s2 = g_srt_src[j + 2], s3 = g_srt_src[j + 3];
        uint4 kv0 = KV4[(size_t)s0 * 32 + lane];
        uint4 kv1 = KV4[(size_t)s1 * 32 + lane];
        uint4 kv2 = KV4[(size_t)s2 * 32 + lane];
        uint4 kv3 = KV4[(size_t)s3 * 32 + lane];
        float sc0 = edge_score_kv(kv0, q);
        float sc1 = edge_score_kv(kv1, q);
        float sc2 = edge_score_kv(kv2, q);
        float sc3 = edge_score_kv(kv3, q);
        acc_kv(acc, kv0, sc0); acc_kv(acc, kv1, sc1);
        acc_kv(acc, kv2, sc2); acc_kv(acc, kv3, sc3);
        z += (sc0 + sc1) + (sc2 + sc3);
    }
    for (; j < end; j++) {
        int s = g_srt_src[j];
        uint4 kv = KV4[(size_t)s * 32 + lane];
        float sc = edge_score_kv(kv, q);
        acc_kv(acc, kv, sc);
        z += sc;
    }

    float inv = 1.f / (z + 1e-6f);
    acc.x *= inv; acc.y *= inv; acc.z *= inv; acc.w *= inv;
    *(float4*)&out[(size_t)node * 128 + (lane << 2)] = acc;
}

// ---------------- launcher ----------------
extern "C" void kernel_launch(void* const* d_in, const int* in_sizes, int n_in,
                              void* d_out, int out_size) {
    const float* h  = (const float*)d_in[0];
    const float* Wq = (const float*)d_in[1];
    const float* bq = (const float*)d_in[2];
    const float* Wk = (const float*)d_in[3];
    const float* bk = (const float*)d_in[4];
    const float* Wv = (const float*)d_in[5];
    const float* bv = (const float*)d_in[6];
    const int*  src = (const int*)d_in[7];
    const int*  dst = (const int*)d_in[8];
    const int E = in_sizes[7];
    float* out = (float*)d_out;

    setup_kernel<<<(N_NODES + 255) / 256, 256>>>(Wq, Wk, Wv);
    degree_kernel<<<(E + 255) / 256, 256>>>(src, dst, E);
    scan_local<<<NCHUNK, 1024>>>();
    finalize_csr<<<(N_NODES + 255) / 256, 256>>>();

    int nmax = (E > NH / 4) ? E : NH / 4;
    bucket_prescale<<<(nmax + 255) / 256, 256>>>(h, src, dst, E);

    int nwblocks = (N_NODES * 32 + 255) / 256;
    agg_gather<<<nwblocks, 256>>>();

    dim3 gg((N_NODES + 127) / 128, 3);
    gemm_qkv_mma<<<gg, 256>>>(bq, bk, bv);

    attn_gather<<<nwblocks, 256>>>(out);
}

// round 17
// speedup vs baseline: 1.5186x; 1.0620x over previous
#include <cuda_runtime.h>
#include <cuda_bf16.h>
#include <cuda_fp16.h>
#include <math.h>

#define N_NODES 50000
#define HIDDEN  128
#define HEADS   8
#define NH      (N_NODES * HIDDEN)
#define E_MAX   1600000
#define NCHUNK  ((N_NODES + 1023) / 1024)   // 49

// ---------------- scratch (device globals: allocation-free rule) ----------------
__device__ int   g_cnt_out[N_NODES];
__device__ int   g_cnt_in[N_NODES];
__device__ int   g_rowptr[N_NODES + 1];
__device__ int   g_cur[N_NODES];
__device__ __align__(16) int g_srt_src[E_MAX];
__device__ int   g_chunk[64];
__device__ float g_norm_out[N_NODES];
__device__ float g_norm_in[N_NODES];
__device__ __half g_hh[NH];                 // h * norm_out, fp16 (12.8 MB)
__device__ __half g_aggh[NH];               // aggregated features, fp16 (12.8 MB)
__device__ float g_Qf[NH];                  // Q fp32 (25.6 MB)
__device__ __half g_KVh[2 * NH];            // K|V interleaved per lane: 8 halfs = 4K + 4V (25.6 MB)
__device__ __half g_Wt_hi[3][128 * 128];    // W^T split-fp16 high parts
__device__ __half g_Wt_lo[3][128 * 128];    // W^T split-fp16 low (residual) parts

// ---------------- 0: fused setup: zero counters + W -> transposed split-fp16 ----------------
__global__ void setup_kernel(const float* __restrict__ Wq, const float* __restrict__ Wk,
                             const float* __restrict__ Wv) {
    int t = blockIdx.x * 256 + threadIdx.x;
    if (t < N_NODES) { g_cnt_out[t] = 0; g_cnt_in[t] = 0; }
    if (t < 3 * 128 * 128) {
        int mat = t >> 14, rem = t & 16383;
        int n = rem >> 7, k = rem & 127;
        const float* W = (mat == 0) ? Wq : (mat == 1) ? Wk : Wv;
        float x = W[k * 128 + n];
        __half hi = __float2half(x);
        g_Wt_hi[mat][n * 128 + k] = hi;
        g_Wt_lo[mat][n * 128 + k] = __float2half(x - __half2float(hi));
    }
}

// ---------------- 1: degree histograms ----------------
__global__ void degree_kernel(const int* __restrict__ src, const int* __restrict__ dst, int E) {
    int e = blockIdx.x * blockDim.x + threadIdx.x;
    if (e < E) {
        atomicAdd(&g_cnt_out[src[e]], 1);
        atomicAdd(&g_cnt_in[dst[e]], 1);
    }
}

// ---------------- 2a: per-1024-chunk inclusive scan of in-degrees ----------------
__global__ void scan_local() {
    __shared__ int wsum[32];
    const int tid = threadIdx.x, lane = tid & 31, wid = tid >> 5;
    int i = blockIdx.x * 1024 + tid;
    int x = (i < N_NODES) ? g_cnt_in[i] : 0;
    #pragma unroll
    for (int o = 1; o < 32; o <<= 1) {
        int t = __shfl_up_sync(0xffffffffu, x, o);
        if (lane >= o) x += t;
    }
    if (lane == 31) wsum[wid] = x;
    __syncthreads();
    if (wid == 0) {
        int w = wsum[lane];
        #pragma unroll
        for (int o = 1; o < 32; o <<= 1) {
            int t = __shfl_up_sync(0xffffffffu, w, o);
            if (lane >= o) w += t;
        }
        wsum[lane] = w;
    }
    __syncthreads();
    int incl = x + (wid > 0 ? wsum[wid - 1] : 0);
    if (i < N_NODES) g_rowptr[i + 1] = incl;
    if (tid == 1023) g_chunk[blockIdx.x] = incl;
}

// ---------------- 2b: finalize rowptr + cursors + norms (chunk scan inlined per-block) ----------------
__global__ void finalize_csr() {
    __shared__ int pref[64];
    const int tid = threadIdx.x;
    if (tid < 64) pref[tid] = (tid < NCHUNK) ? g_chunk[tid] : 0;
    __syncthreads();
    #pragma unroll
    for (int off = 1; off < 64; off <<= 1) {
        int v = 0;
        if (tid < 64 && tid >= off) v = pref[tid - off];
        __syncthreads();
        if (tid < 64) pref[tid] += v;
        __syncthreads();
    }
    int i = blockIdx.x * blockDim.x + tid;
    if (i < N_NODES) {
        int c = i >> 10;
        int inc = g_rowptr[i + 1] + ((c > 0) ? pref[c - 1] : 0);
        g_rowptr[i + 1] = inc;
        int cin = g_cnt_in[i];
        g_cur[i] = inc - cin;
        g_norm_in[i]  = rsqrtf(fmaxf((float)cin, 1.f));
        g_norm_out[i] = rsqrtf(fmaxf((float)g_cnt_out[i], 1.f));
        if (i == 0) g_rowptr[0] = 0;
    }
}

// ---------------- 3: fused counting-sort bucket fill + prescale h*norm_out -> fp16 ----------------
__global__ void bucket_prescale(const float* __restrict__ h,
                                const int* __restrict__ src, const int* __restrict__ dst, int E) {
    int i = blockIdx.x * 256 + threadIdx.x;
    if (i < E) {
        int p = atomicAdd(&g_cur[dst[i]], 1);
        g_srt_src[p] = src[i];
    }
    if (i < NH / 4) {
        int node = i >> 5;
        float no = g_norm_out[node];
        float4 a = ((const float4*)h)[i];
        __half2 h0 = __floats2half2_rn(a.x * no, a.y * no);
        __half2 h1 = __floats2half2_rn(a.z * no, a.w * no);
        uint2 o;
        o.x = *reinterpret_cast<unsigned*>(&h0);
        o.y = *reinterpret_cast<unsigned*>(&h1);
        ((uint2*)g_hh)[i] = o;
    }
}

// ---------------- 4: gather-aggregate (fp16 prescaled h, fp16 output) ----------------
__device__ __forceinline__ void acc_h2(float4& acc, uint2 raw) {
    float2 f0 = __half22float2(*reinterpret_cast<__half2*>(&raw.x));
    float2 f1 = __half22float2(*reinterpret_cast<__half2*>(&raw.y));
    acc.x += f0.x; acc.y += f0.y; acc.z += f1.x; acc.w += f1.y;
}

__global__ __launch_bounds__(256) void agg_gather() {
    int node = (blockIdx.x * blockDim.x + threadIdx.x) >> 5;
    int lane = threadIdx.x & 31;
    if (node >= N_NODES) return;
    int beg = g_rowptr[node], end = g_rowptr[node + 1];
    const uint2* h2 = (const uint2*)g_hh;
    float4 acc = make_float4(0.f, 0.f, 0.f, 0.f);
    int j = beg;
    for (; j + 4 <= end; j += 4) {
        int s0 = g_srt_src[j], s1 = g_srt_src[j + 1], s2 = g_srt_src[j + 2], s3 = g_srt_src[j + 3];
        uint2 a = h2[(size_t)s0 * 32 + lane];
        uint2 b = h2[(size_t)s1 * 32 + lane];
        uint2 c = h2[(size_t)s2 * 32 + lane];
        uint2 d = h2[(size_t)s3 * 32 + lane];
        acc_h2(acc, a); acc_h2(acc, b); acc_h2(acc, c); acc_h2(acc, d);
    }
    for (; j < end; j++) {
        int s = g_srt_src[j];
        acc_h2(acc, h2[(size_t)s * 32 + lane]);
    }
    float ni = g_norm_in[node];
    __half2 o0 = __floats2half2_rn(acc.x * ni, acc.y * ni);
    __half2 o1 = __floats2half2_rn(acc.z * ni, acc.w * ni);
    uint2 ov;
    ov.x = *reinterpret_cast<unsigned*>(&o0);
    ov.y = *reinterpret_cast<unsigned*>(&o1);
    ((uint2*)g_aggh)[(size_t)node * 32 + lane] = ov;
}

// ---------------- 5: QKV GEMM: fp16 A x split-fp16 W, 2 MMAs per product ----------------
__device__ __forceinline__ void mma16816f(float* c, const unsigned* a, unsigned b0, unsigned b1) {
    asm volatile(
        "mma.sync.aligned.m16n8k16.row.col.f32.f16.f16.f32 "
        "{%0,%1,%2,%3}, {%4,%5,%6,%7}, {%8,%9}, {%0,%1,%2,%3};\n"
        : "+f"(c[0]), "+f"(c[1]), "+f"(c[2]), "+f"(c[3])
        : "r"(a[0]), "r"(a[1]), "r"(a[2]), "r"(a[3]), "r"(b0), "r"(b1));
}

// M-tile 128 x N 128, K streamed in 32-chunks. 8 warps, warp w owns rows [16w,16w+16).
__global__ __launch_bounds__(256, 2) void gemm_qkv_mma(
    const float* __restrict__ bq, const float* __restrict__ bk, const float* __restrict__ bv)
{
    const int mat = blockIdx.y;
    const float* bias = (mat == 0) ? bq : (mat == 1) ? bk : bv;
    const __half* WtH = g_Wt_hi[mat];
    const __half* WtL = g_Wt_lo[mat];

    // stride 40 halfs (20 words): conflict-free frag loads
    __shared__ __half sA[128 * 40];
    __shared__ __half sB_hi[128 * 40];
    __shared__ __half sB_lo[128 * 40];

    const int tid = threadIdx.x;
    const int warp = tid >> 5, lane = tid & 31;
    const int g = lane >> 2, tg = lane & 3;
    const int row0 = blockIdx.x * 128;

    float acc[16][4];
    #pragma unroll
    for (int i = 0; i < 16; i++)
        #pragma unroll
        for (int j = 0; j < 4; j++) acc[i][j] = 0.f;

    const int r = tid >> 1;           // 0..127 (A row / B n-row)
    const int hh = tid & 1;           // half: 16 elems each

    for (int k0 = 0; k0 < 128; k0 += 32) {
        // --- A tile [128 rows x 32 k], fp16 direct copy (no conversion) ---
        int arow = row0 + r;
        int4 a0 = make_int4(0, 0, 0, 0), a1 = make_int4(0, 0, 0, 0);
        if (arow < N_NODES) {
            const int4* ap = (const int4*)(g_aggh + (size_t)arow * 128 + k0 + hh * 16);
            a0 = ap[0]; a1 = ap[1];
        }
        *(int4*)&sA[r * 40 + hh * 16]     = a0;
        *(int4*)&sA[r * 40 + hh * 16 + 8] = a1;

        // --- pre-split W tile [128 n x 32 k] ---
        const int4* srcH = (const int4*)(WtH + r * 128 + k0 + hh * 16);
        const int4* srcL = (const int4*)(WtL + r * 128 + k0 + hh * 16);
        *(int4*)&sB_hi[r * 40 + hh * 16]     = srcH[0];
        *(int4*)&sB_hi[r * 40 + hh * 16 + 8] = srcH[1];
        *(int4*)&sB_lo[r * 40 + hh * 16]     = srcL[0];
        *(int4*)&sB_lo[r * 40 + hh * 16 + 8] = srcL[1];
        __syncthreads();

        const unsigned* pA  = (const unsigned*)sA;
        const unsigned* pBH = (const unsigned*)sB_hi;
        const unsigned* pBL = (const unsigned*)sB_lo;
        const int ra = warp * 16 + g;

        #pragma unroll
        for (int kw = 0; kw <= 8; kw += 8) {   // two k16 sub-steps (word offset 0, 8)
            unsigned a[4];
            a[0] = pA[ra * 20 + kw + tg];
            a[1] = pA[(ra + 8) * 20 + kw + tg];
            a[2] = pA[ra * 20 + kw + tg + 4];
            a[3] = pA[(ra + 8) * 20 + kw + tg + 4];
            #pragma unroll
            for (int nt = 0; nt < 16; nt++) {
                int nb = nt * 8 + g;
                unsigned bH0 = pBH[nb * 20 + kw + tg];
                unsigned bH1 = pBH[nb * 20 + kw + tg + 4];
                unsigned bL0 = pBL[nb * 20 + kw + tg];
                unsigned bL1 = pBL[nb * 20 + kw + tg + 4];
                mma16816f(acc[nt], a, bH0, bH1);
                mma16816f(acc[nt], a, bL0, bL1);
            }
        }
        __syncthreads();
    }

    // --- epilogue: bias + relu; Q fp32; K/V fp16 interleaved per lane ---
    const int gr0 = row0 + warp * 16 + g;
    const int gr1 = gr0 + 8;
    #pragma unroll
    for (int nt = 0; nt < 16; nt++) {
        int c = nt * 8 + tg * 2;
        float2 bb = *(const float2*)&bias[c];
        float v0 = fmaxf(acc[nt][0] + bb.x, 0.f);
        float v1 = fmaxf(acc[nt][1] + bb.y, 0.f);
        float v2 = fmaxf(acc[nt][2] + bb.x, 0.f);
        float v3 = fmaxf(acc[nt][3] + bb.y, 0.f);
        if (mat == 0) {
            if (gr0 < N_NODES) *(float2*)&g_Qf[(size_t)gr0 * 128 + c] = make_float2(v0, v1);
            if (gr1 < N_NODES) *(float2*)&g_Qf[(size_t)gr1 * 128 + c] = make_float2(v2, v3);
        } else {
            size_t off = ((size_t)(c >> 2) << 3) + (c & 3) + ((mat == 2) ? 4 : 0);
            if (gr0 < N_NODES) *(__half2*)&g_KVh[(size_t)gr0 * 256 + off] = __floats2half2_rn(v0, v1);
            if (gr1 < N_NODES) *(__half2*)&g_KVh[(size_t)gr1 * 256 + off] = __floats2half2_rn(v2, v3);
        }
    }
}

// ---------------- 6: gather-attention + finalize ----------------
// per lane: one uint4 = 4 K-feats + 4 V-feats (fp16). fp32 score math (proven config).
__device__ __forceinline__ float edge_score_kv(uint4 kv, float4 q) {
    float2 k01 = __half22float2(*reinterpret_cast<__half2*>(&kv.x));
    float2 k23 = __half22float2(*reinterpret_cast<__half2*>(&kv.y));
    float p = k01.x * q.x + k01.y * q.y + k23.x * q.z + k23.y * q.w;
    p += __shfl_xor_sync(0xffffffffu, p, 1);
    p += __shfl_xor_sync(0xffffffffu, p, 2);
    return __expf(fminf(fmaxf(p * 0.25f, -10.f), 10.f));
}

__device__ __forceinline__ void acc_kv(float4& acc, uint4 kv, float sc) {
    float2 f0 = __half22float2(*reinterpret_cast<__half2*>(&kv.z));
    float2 f1 = __half22float2(*reinterpret_cast<__half2*>(&kv.w));
    acc.x += f0.x * sc; acc.y += f0.y * sc; acc.z += f1.x * sc; acc.w += f1.y * sc;
}

__global__ __launch_bounds__(256) void attn_gather(float* __restrict__ out) {
    int node = (blockIdx.x * blockDim.x + threadIdx.x) >> 5;
    int lane = threadIdx.x & 31;
    if (node >= N_NODES) return;
    int beg = g_rowptr[node], end = g_rowptr[node + 1];

    const float4* Q4 = (const float4*)g_Qf;
    const uint4* KV4 = (const uint4*)g_KVh;

    float4 q = Q4[(size_t)node * 32 + lane];
    float4 acc = make_float4(0.f, 0.f, 0.f, 0.f);
    float z = 0.f;

    int j = beg;
    for (; j + 4 <= end; j += 4) {
        int s0 = g_srt_src[j], s1 = g_srt_src[j + 1], s2 = g_srt_src[j + 2], s3 = g_srt_src[j + 3];
        uint4 kv0 = KV4[(size_t)s0 * 32 + lane];
        uint4 kv1 = KV4[(size_t)s1 * 32 + lane];
        uint4 kv2 = KV4[(size_t)s2 * 32 + lane];
        uint4 kv3 = KV4[(size_t)s3 * 32 + lane];
        float sc0 = edge_score_kv(kv0, q);
        float sc1 = edge_score_kv(kv1, q);
        float sc2 = edge_score_kv(kv2, q);
        float sc3 = edge_score_kv(kv3, q);
        acc_kv(acc, kv0, sc0); acc_kv(acc, kv1, sc1);
        acc_kv(acc, kv2, sc2); acc_kv(acc, kv3, sc3);
        z += (sc0 + sc1) + (sc2 + sc3);
    }
    for (; j < end; j++) {
        int s = g_srt_src[j];
        uint4 kv = KV4[(size_t)s * 32 + lane];
        float sc = edge_score_kv(kv, q);
        acc_kv(acc, kv, sc);
        z += sc;
    }

    float inv = 1.f / (z + 1e-6f);
    acc.x *= inv; acc.y *= inv; acc.z *= inv; acc.w *= inv;
    *(float4*)&out[(size_t)node * 128 + (lane << 2)] = acc;
}

// ---------------- launcher ----------------
extern "C" void kernel_launch(void* const* d_in, const int* in_sizes, int n_in,
                              void* d_out, int out_size) {
    const float* h  = (const float*)d_in[0];
    const float* Wq = (const float*)d_in[1];
    const float* bq = (const float*)d_in[2];
    const float* Wk = (const float*)d_in[3];
    const float* bk = (const float*)d_in[4];
    const float* Wv = (const float*)d_in[5];
    const float* bv = (const float*)d_in[6];
    const int*  src = (const int*)d_in[7];
    const int*  dst = (const int*)d_in[8];
    const int E = in_sizes[7];
    float* out = (float*)d_out;

    setup_kernel<<<(N_NODES + 255) / 256, 256>>>(Wq, Wk, Wv);
    degree_kernel<<<(E + 255) / 256, 256>>>(src, dst, E);
    scan_local<<<NCHUNK, 1024>>>();
    finalize_csr<<<(N_NODES + 255) / 256, 256>>>();

    int nmax = (E > NH / 4) ? E : NH / 4;
    bucket_prescale<<<(nmax + 255) / 256, 256>>>(h, src, dst, E);

    int nwblocks = (N_NODES * 32 + 255) / 256;
    agg_gather<<<nwblocks, 256>>>();

    dim3 gg((N_NODES + 127) / 128, 3);
    gemm_qkv_mma<<<gg, 256>>>(bq, bk, bv);

    attn_gather<<<nwblocks, 256>>>(out);
}